// round 8
// baseline (speedup 1.0000x reference)
#include <cuda_runtime.h>
#include <math.h>
#include <stdint.h>

#define T_LEN 512
#define BATCH 64
#define ISZ   256
#define HID   512
#define GH    2048   // 4*HID, gate order f,i,o,c
#define NCTA  128
#define BG    16     // batch per group
#define NGRP  4      // batch groups (independent recurrences)

// ---------------- device scratch (no allocations allowed) ----------------
__device__ float g_gx[(size_t)T_LEN * GH * BATCH];  // [t][n=g*512+h][b] (bx+bh folded)
__device__ float g_h[2][NGRP][HID * BG];            // double-buffered h, [gid][hid][b_local]
__device__ volatile unsigned g_flags[NGRP * 32];    // per-CTA step counters

// ---------------- packed f32x2 helpers (sm_100+) ----------------
union F2U { float2 f; unsigned long long u; };
__device__ __forceinline__ float2 ffma2(float2 a, float2 b, float2 c) {
    F2U A, B, C, D; A.f = a; B.f = b; C.f = c;
    asm("fma.rn.f32x2 %0, %1, %2, %3;" : "=l"(D.u) : "l"(A.u), "l"(B.u), "l"(C.u));
    return D.f;
}
__device__ __forceinline__ float fast_sigmoid(float x) {
    return __fdividef(1.0f, 1.0f + __expf(-x));
}
__device__ __forceinline__ float fast_tanh(float x) {
    return __fdividef(2.0f, 1.0f + __expf(-2.0f * x)) - 1.0f;
}

// ---------------- mbarrier helpers ----------------
__device__ __forceinline__ unsigned smem_u32(const void* p) {
    return (unsigned)__cvta_generic_to_shared(p);
}
__device__ __forceinline__ void mbar_init(unsigned bar, unsigned count) {
    asm volatile("mbarrier.init.shared.b64 [%0], %1;" :: "r"(bar), "r"(count) : "memory");
}
__device__ __forceinline__ void mbar_expect_tx(unsigned bar, unsigned bytes) {
    asm volatile("mbarrier.arrive.expect_tx.shared.b64 _, [%0], %1;"
                 :: "r"(bar), "r"(bytes) : "memory");
}
__device__ __forceinline__ void bulk_g2s(unsigned dst, const void* src, unsigned bytes, unsigned bar) {
    asm volatile("cp.async.bulk.shared::cta.global.mbarrier::complete_tx::bytes [%0], [%1], %2, [%3];"
                 :: "r"(dst), "l"(src), "r"(bytes), "r"(bar) : "memory");
}
__device__ __forceinline__ void mbar_wait(unsigned bar, unsigned parity) {
    asm volatile(
        "{\n\t"
        ".reg .pred P;\n\t"
        "WAIT_%=:\n\t"
        "mbarrier.try_wait.parity.acquire.cta.shared::cta.b64 P, [%0], %1;\n\t"
        "@!P bra WAIT_%=;\n\t"
        "}"
        :: "r"(bar), "r"(parity) : "memory");
}

// ---------------- init: zero h buffers + flags each replay ----------------
__global__ void init_state_kernel() {
    int idx = blockIdx.x * blockDim.x + threadIdx.x;
    if (idx < 2 * NGRP * HID * BG) ((float*)g_h)[idx] = 0.0f;
    if (idx < NGRP * 32) g_flags[idx] = 0u;
}

// ---------------- gx = x @ Wx^T + (bx + bh)  -> g_gx[t][n][b] ----------------
__global__ __launch_bounds__(256) void gx_kernel(const float* __restrict__ x,
                                                 const float* __restrict__ Wx,
                                                 const float* __restrict__ bx,
                                                 const float* __restrict__ bh) {
    extern __shared__ float sm[];
    float* x_s = sm;               // [256][65] padded transpose
    float* Ws  = sm + 256 * 65;    // [32][256]
    const int tid = threadIdx.x;
    const int t   = blockIdx.y;
    const int n0  = blockIdx.x * 32;

    const float* xt = x + (size_t)t * BATCH * ISZ;
    #pragma unroll 4
    for (int r = 0; r < 64; r++) {
        int idx = r * 256 + tid;
        int b = idx >> 8;
        int i = idx & 255;
        x_s[i * 65 + b] = xt[idx];
    }
    const float* Wrow = Wx + (size_t)n0 * ISZ;
    #pragma unroll 4
    for (int r = 0; r < 32; r++) {
        int idx = r * 256 + tid;
        Ws[idx] = Wrow[idx];
    }
    __syncthreads();

    const int b  = tid & 63;
    const int ng = tid >> 6;
    float acc[8];
    #pragma unroll
    for (int j = 0; j < 8; j++) acc[j] = 0.0f;

    const float4* Ws4 = (const float4*)(Ws + (ng * 8) * ISZ);
    #pragma unroll 2
    for (int k4 = 0; k4 < 64; k4++) {
        const int k = k4 * 4;
        const float xa = x_s[(k + 0) * 65 + b];
        const float xb = x_s[(k + 1) * 65 + b];
        const float xc = x_s[(k + 2) * 65 + b];
        const float xd = x_s[(k + 3) * 65 + b];
        #pragma unroll
        for (int j = 0; j < 8; j++) {
            float4 w = Ws4[j * 64 + k4];
            acc[j] += w.x * xa;
            acc[j] += w.y * xb;
            acc[j] += w.z * xc;
            acc[j] += w.w * xd;
        }
    }

    const size_t base = ((size_t)t * GH + n0 + ng * 8) * BATCH + b;
    #pragma unroll
    for (int j = 0; j < 8; j++) {
        const int n = n0 + ng * 8 + j;
        g_gx[base + (size_t)j * BATCH] = acc[j] + __ldg(&bx[n]) + __ldg(&bh[n]);
    }
}

// ---------------- persistent recurrence kernel ----------------
// 4 independent batch groups x 32 CTAs. bid = gid*32 + rid.
// CTA owns h-units [rid*16, rid*16+16) x batches [gid*16, gid*16+16).
// Smem Wsp[k 512][hu 16][g 4] -> lane reads a cell's 4 gates as one float4.
// Warp (khq 0..3, rh 0..1); lane (rg 0..3, bp 0..7):
//   hu pair = rh*8 + rg*2 + {0,1}; batches (2bp, 2bp+1); k range khq*128..+128.
// k-quarter q of h produced by CTAs rid in [8q, 8q+8): stager warp (q, rh=0)
// polls those 8 per-CTA flags (one lane each), then bulk-copies 8 KB.
__global__ __launch_bounds__(256, 1) void lstm_persistent(
        const float* __restrict__ Wh,
        float* __restrict__ h_seq,
        float* __restrict__ out_hlast,
        float* __restrict__ out_clast) {
    extern __shared__ float sm[];
    float*  Wsp = sm;                         // [512][64]  128 KB
    float*  hs  = sm + 512 * 64;              // [512][16]   32 KB
    float4* red4 = (float4*)(hs + HID * BG);  // [4 q][16 hu][16 b] f4 = 16 KB
    unsigned long long* mbar = (unsigned long long*)(red4 + 1024);

    const int tid  = threadIdx.x;
    const int lane = tid & 31;
    const int warp = tid >> 5;
    const int bp   = lane & 7;
    const int rg   = lane >> 3;               // 0..3
    const int rh   = warp & 1;
    const int khq  = warp >> 1;
    const int bid  = blockIdx.x;
    const int gid  = bid >> 5;
    const int rid  = bid & 31;
    const int hu_a = rh * 8 + rg * 2;          // local h-unit pair
    const bool is_stager_warp = (rh == 0);

    // ---- stage Wsp once: Wsp[k*64 + hu*4 + g] = Wh[(g*512 + rid*16+hu)]][k]
    for (int it = 0; it < 128; it++) {
        int idx = it * 256 + tid;              // 0..32767 = r*512 + k
        int r = idx >> 9, k = idx & 511;
        int hu = r >> 2, g = r & 3;
        Wsp[k * 64 + r] = Wh[((size_t)(g * HID + rid * 16 + hu)) * HID + k];
    }
    if (tid == 0) {
        #pragma unroll
        for (int q = 0; q < 4; q++) mbar_init(smem_u32(&mbar[q]), 1);
    }

    // epilogue threads: tid < 128 -> cell pair (ehu = tid>>3, ebp = tid&7)
    const bool epi = (tid < 128);
    const int ehu = tid >> 3;                  // 0..15
    const int ebp = tid & 7;                   // 0..7
    const int ehid = rid * 16 + ehu;           // global hidden index
    const int ebg  = gid * BG + 2 * ebp;       // global batch index
    float c0 = 0.0f, c1 = 0.0f;

    const unsigned my_bar  = smem_u32(&mbar[khq]);
    const unsigned hs_dst0 = smem_u32(hs);
    const volatile unsigned* my_flags = &g_flags[gid * 32 + khq * 8];

    __syncthreads();

    int cur = 0;
    for (int t = 0; t < T_LEN; t++) {
        // ---- gx prefetch (h-independent; overlaps the flag poll)
        float2 gxf, gxi, gxo, gxc;
        if (epi) {
            const float* gp = g_gx + ((size_t)t * GH + ehid) * BATCH + ebg;
            gxf = __ldg((const float2*)(gp + (size_t)0 * HID * BATCH));
            gxi = __ldg((const float2*)(gp + (size_t)1 * HID * BATCH));
            gxo = __ldg((const float2*)(gp + (size_t)2 * HID * BATCH));
            gxc = __ldg((const float2*)(gp + (size_t)3 * HID * BATCH));
        }

        // ---- stager warp: poll this quarter's 8 producers, then copy 8 KB
        if (is_stager_warp) {
            if (t > 0 && lane < 8) {
                while (my_flags[lane] < (unsigned)t) { __nanosleep(32); }
            }
            __syncwarp();
            if (lane == 0) {
                mbar_expect_tx(my_bar, 8192u);
                bulk_g2s(hs_dst0 + (unsigned)khq * 8192u,
                         (const char*)(g_h[cur][gid]) + (unsigned)khq * 8192u,
                         8192u, my_bar);
            }
        }

        // ---- wait only for this warp's k-quarter
        mbar_wait(my_bar, (unsigned)(t & 1));

        // ---- compute: 128 k x (2 hu x 4 gates x 2 batches)
        float2 A0fiA = make_float2(0.f, 0.f), A0ocA = A0fiA, A1fiA = A0fiA, A1ocA = A0fiA;
        float2 A0fiB = A0fiA, A0ocB = A0fiA, A1fiB = A0fiA, A1ocB = A0fiA;

        const float* wP = Wsp + (khq * 128) * 64 + hu_a * 4;
        const float* hP = hs + (khq * 128) * 16 + 2 * bp;

        #pragma unroll 4
        for (int kl = 0; kl < 128; kl++) {
            const float4 wA = *(const float4*)(wP);       // hu_a: (f,i,o,c)
            const float4 wB = *(const float4*)(wP + 4);   // hu_a+1
            const float2 hv = *(const float2*)(hP);
            const float2 d0 = make_float2(hv.x, hv.x);
            const float2 d1 = make_float2(hv.y, hv.y);
            const float2 wAfi = make_float2(wA.x, wA.y);
            const float2 wAoc = make_float2(wA.z, wA.w);
            const float2 wBfi = make_float2(wB.x, wB.y);
            const float2 wBoc = make_float2(wB.z, wB.w);
            A0fiA = ffma2(wAfi, d0, A0fiA);
            A0ocA = ffma2(wAoc, d0, A0ocA);
            A1fiA = ffma2(wAfi, d1, A1fiA);
            A1ocA = ffma2(wAoc, d1, A1ocA);
            A0fiB = ffma2(wBfi, d0, A0fiB);
            A0ocB = ffma2(wBoc, d0, A0ocB);
            A1fiB = ffma2(wBfi, d1, A1fiB);
            A1ocB = ffma2(wBoc, d1, A1ocB);
            wP += 64;
            hP += 16;
        }

        // ---- scatter partials: red4[(q*16 + hu)*16 + b] = (f,i,o,c) accs
        {
            float4* r = red4 + ((khq * 16 + hu_a) * 16) + 2 * bp;
            r[0]  = make_float4(A0fiA.x, A0fiA.y, A0ocA.x, A0ocA.y);
            r[1]  = make_float4(A1fiA.x, A1fiA.y, A1ocA.x, A1ocA.y);
            r[16] = make_float4(A0fiB.x, A0fiB.y, A0ocB.x, A0ocB.y);
            r[17] = make_float4(A1fiB.x, A1fiB.y, A1ocB.x, A1ocB.y);
        }
        __syncthreads();

        // ---- reduce 4 k-quarters + gates + publish (epi threads)
        if (epi) {
            const float4* q0 = red4 + (0 * 16 + ehu) * 16 + 2 * ebp;
            const float4* q1 = red4 + (1 * 16 + ehu) * 16 + 2 * ebp;
            const float4* q2 = red4 + (2 * 16 + ehu) * 16 + 2 * ebp;
            const float4* q3 = red4 + (3 * 16 + ehu) * 16 + 2 * ebp;
            float4 s0 = q0[0], s1 = q0[1];
            float4 v;
            v = q1[0]; s0.x += v.x; s0.y += v.y; s0.z += v.z; s0.w += v.w;
            v = q2[0]; s0.x += v.x; s0.y += v.y; s0.z += v.z; s0.w += v.w;
            v = q3[0]; s0.x += v.x; s0.y += v.y; s0.z += v.z; s0.w += v.w;
            v = q1[1]; s1.x += v.x; s1.y += v.y; s1.z += v.z; s1.w += v.w;
            v = q2[1]; s1.x += v.x; s1.y += v.y; s1.z += v.z; s1.w += v.w;
            v = q3[1]; s1.x += v.x; s1.y += v.y; s1.z += v.z; s1.w += v.w;

            // s = (f, i, o, c) preacts; gx already contains bx + bh
            const float pf0 = s0.x + gxf.x, pf1 = s1.x + gxf.y;
            const float pi0 = s0.y + gxi.x, pi1 = s1.y + gxi.y;
            const float po0 = s0.z + gxo.x, po1 = s1.z + gxo.y;
            const float pc0 = s0.w + gxc.x, pc1 = s1.w + gxc.y;

            const float f0 = fast_sigmoid(pf0), f1 = fast_sigmoid(pf1);
            const float i0 = fast_sigmoid(pi0), i1 = fast_sigmoid(pi1);
            const float o0 = fast_sigmoid(po0), o1 = fast_sigmoid(po1);
            const float qq0 = fast_tanh(pc0),   qq1 = fast_tanh(pc1);

            c0 = f0 * c0 + i0 * qq0;
            c1 = f1 * c1 + i1 * qq1;
            const float hn0 = o0 * fast_tanh(c0);
            const float hn1 = o1 * fast_tanh(c1);

            // publish next-step h (the only cross-CTA dependency)
            __stcg((float2*)(g_h[cur ^ 1][gid] + (rid * 16 + ehu) * BG + 2 * ebp),
                   make_float2(hn0, hn1));

            // epi-only barrier, fence, release this CTA's flag
            asm volatile("bar.sync 1, 128;" ::: "memory");
            if (tid == 0) {
                __threadfence();
                g_flags[gid * 32 + rid] = (unsigned)(t + 1);
            }

            // off-critical-path outputs
            float* so = h_seq + ((size_t)t * BATCH + ebg) * HID + ehid;
            so[0]   = hn0;
            so[HID] = hn1;
            if (t == T_LEN - 1) {
                out_hlast[(size_t)ebg * HID + ehid]       = hn0;
                out_hlast[(size_t)(ebg + 1) * HID + ehid] = hn1;
                out_clast[(size_t)ebg * HID + ehid]       = c0;
                out_clast[(size_t)(ebg + 1) * HID + ehid] = c1;
            }
        }

        cur ^= 1;
    }
}

// ---------------- launch ----------------
extern "C" void kernel_launch(void* const* d_in, const int* in_sizes, int n_in,
                              void* d_out, int out_size) {
    const float* x  = (const float*)d_in[0];
    const float* Wx = (const float*)d_in[1];
    const float* bx = (const float*)d_in[2];
    const float* Wh = (const float*)d_in[3];
    const float* bh = (const float*)d_in[4];

    float* out       = (float*)d_out;
    float* out_hlast = out + (size_t)T_LEN * BATCH * HID;
    float* out_clast = out_hlast + (size_t)BATCH * HID;

    const int gx_smem = (256 * 65 + 32 * 256) * sizeof(float);   // 99328 B
    const int ps_smem = (512 * 64 + 512 * 16 + 4096) * sizeof(float) + 64; // ~180.3 KB
    cudaFuncSetAttribute(gx_kernel,       cudaFuncAttributeMaxDynamicSharedMemorySize, gx_smem);
    cudaFuncSetAttribute(lstm_persistent, cudaFuncAttributeMaxDynamicSharedMemorySize, ps_smem);

    init_state_kernel<<<128, 512>>>();
    gx_kernel<<<dim3(64, 512), 256, gx_smem>>>(x, Wx, bx, bh);
    lstm_persistent<<<NCTA, 256, ps_smem>>>(Wh, out, out_hlast, out_clast);
}

// round 9
// speedup vs baseline: 1.4935x; 1.4935x over previous
#include <cuda_runtime.h>
#include <math.h>
#include <stdint.h>

#define T_LEN 512
#define BATCH 64
#define ISZ   256
#define HID   512
#define GH    2048   // 4*HID, gate order f,i,o,c
#define NCTA  128

// ---------------- device scratch (no allocations allowed) ----------------
__device__ float g_gx[(size_t)T_LEN * GH * BATCH];  // [t][n=g*512+h][b] (bx+bh folded in)
__device__ float g_h[2][HID * BATCH];               // double-buffered h, [h][b]
__device__ unsigned g_bars[4];                      // per-group arrival counters
__device__ volatile unsigned g_epochs[4];           // per-group release epochs

// ---------------- packed f32x2 helpers (sm_100+) ----------------
union F2U { float2 f; unsigned long long u; };
__device__ __forceinline__ float2 ffma2(float2 a, float2 b, float2 c) {
    F2U A, B, C, D; A.f = a; B.f = b; C.f = c;
    asm("fma.rn.f32x2 %0, %1, %2, %3;" : "=l"(D.u) : "l"(A.u), "l"(B.u), "l"(C.u));
    return D.f;
}
__device__ __forceinline__ float2 fadd2(float2 a, float2 b) {
    F2U A, B, D; A.f = a; B.f = b;
    asm("add.rn.f32x2 %0, %1, %2;" : "=l"(D.u) : "l"(A.u), "l"(B.u));
    return D.f;
}
__device__ __forceinline__ float fast_sigmoid(float x) {
    return __fdividef(1.0f, 1.0f + __expf(-x));
}
__device__ __forceinline__ float fast_tanh(float x) {
    return __fdividef(2.0f, 1.0f + __expf(-2.0f * x)) - 1.0f;
}

// ---------------- mbarrier helpers ----------------
__device__ __forceinline__ unsigned smem_u32(const void* p) {
    return (unsigned)__cvta_generic_to_shared(p);
}
__device__ __forceinline__ void mbar_init(unsigned bar, unsigned count) {
    asm volatile("mbarrier.init.shared.b64 [%0], %1;" :: "r"(bar), "r"(count) : "memory");
}
__device__ __forceinline__ void mbar_expect_tx(unsigned bar, unsigned bytes) {
    asm volatile("mbarrier.arrive.expect_tx.shared.b64 _, [%0], %1;"
                 :: "r"(bar), "r"(bytes) : "memory");
}
__device__ __forceinline__ void bulk_g2s(unsigned dst, const void* src, unsigned bytes, unsigned bar) {
    asm volatile("cp.async.bulk.shared::cta.global.mbarrier::complete_tx::bytes [%0], [%1], %2, [%3];"
                 :: "r"(dst), "l"(src), "r"(bytes), "r"(bar) : "memory");
}
__device__ __forceinline__ void mbar_wait(unsigned bar, unsigned parity) {
    asm volatile(
        "{\n\t"
        ".reg .pred P;\n\t"
        "WAIT_%=:\n\t"
        "mbarrier.try_wait.parity.acquire.cta.shared::cta.b64 P, [%0], %1;\n\t"
        "@!P bra WAIT_%=;\n\t"
        "}"
        :: "r"(bar), "r"(parity) : "memory");
}

// ---------------- init: zero h buffers + barrier state ----------------
__global__ void init_state_kernel() {
    int idx = blockIdx.x * blockDim.x + threadIdx.x;
    if (idx < 2 * HID * BATCH) ((float*)g_h)[idx] = 0.0f;
    if (idx < 4) { g_bars[idx] = 0; g_epochs[idx] = 0; }
}

// ---------------- gx = x @ Wx^T + (bx + bh)  -> g_gx[t][n][b] ----------------
__global__ __launch_bounds__(256) void gx_kernel(const float* __restrict__ x,
                                                 const float* __restrict__ Wx,
                                                 const float* __restrict__ bx,
                                                 const float* __restrict__ bh) {
    extern __shared__ float sm[];
    float* x_s = sm;               // [256][65] padded transpose
    float* Ws  = sm + 256 * 65;    // [32][256]
    const int tid = threadIdx.x;
    const int t   = blockIdx.y;
    const int n0  = blockIdx.x * 32;

    const float* xt = x + (size_t)t * BATCH * ISZ;
    #pragma unroll 4
    for (int r = 0; r < 64; r++) {
        int idx = r * 256 + tid;
        int b = idx >> 8;
        int i = idx & 255;
        x_s[i * 65 + b] = xt[idx];
    }
    const float* Wrow = Wx + (size_t)n0 * ISZ;
    #pragma unroll 4
    for (int r = 0; r < 32; r++) {
        int idx = r * 256 + tid;
        Ws[idx] = Wrow[idx];
    }
    __syncthreads();

    const int b  = tid & 63;
    const int ng = tid >> 6;
    float acc[8];
    #pragma unroll
    for (int j = 0; j < 8; j++) acc[j] = 0.0f;

    const float4* Ws4 = (const float4*)(Ws + (ng * 8) * ISZ);
    #pragma unroll 2
    for (int k4 = 0; k4 < 64; k4++) {
        const int k = k4 * 4;
        const float xa = x_s[(k + 0) * 65 + b];
        const float xb = x_s[(k + 1) * 65 + b];
        const float xc = x_s[(k + 2) * 65 + b];
        const float xd = x_s[(k + 3) * 65 + b];
        #pragma unroll
        for (int j = 0; j < 8; j++) {
            float4 w = Ws4[j * 64 + k4];
            acc[j] += w.x * xa;
            acc[j] += w.y * xb;
            acc[j] += w.z * xc;
            acc[j] += w.w * xd;
        }
    }

    const size_t base = ((size_t)t * GH + n0 + ng * 8) * BATCH + b;
    #pragma unroll
    for (int j = 0; j < 8; j++) {
        const int n = n0 + ng * 8 + j;
        g_gx[base + (size_t)j * BATCH] = acc[j] + __ldg(&bx[n]) + __ldg(&bh[n]);
    }
}

// ---------------- persistent recurrence kernel ----------------
// 128 CTAs (1/SM) x 512 threads (16 warps). CTA owns 4 hidden units (16 rows).
// h-quarter q produced by CTA group q (bid in [32q, 32q+32)) -> g_epochs[q].
// Warp w: ke = w>>1 (k-eighth, 64 k), hlh = w&1 (hl pair). Lane = batch pair.
// Stager warps 0/5/10/15 (one per SMSP) stage quarter w/5 via cp.async.bulk.
// red race guarded by named barrier 2 (epi arrives after consuming red).
__global__ __launch_bounds__(512, 1) void lstm_persistent(
        const float* __restrict__ Wh,
        float* __restrict__ h_seq,
        float* __restrict__ out_hlast,
        float* __restrict__ out_clast) {
    extern __shared__ float sm[];
    float*  Wsp  = sm;                      // [512 k][16 r(hl,g)]  32 KB
    float*  hs   = sm + 8192;               // [512 k][64 b]       128 KB
    float2* red  = (float2*)(sm + 8192 + 32768);  // [8 ke][4 hl][2 gp][64 b] 32 KB
    unsigned long long* mbar = (unsigned long long*)(sm + 8192 + 32768 + 8192);

    const int tid  = threadIdx.x;
    const int lane = tid & 31;
    const int warp = tid >> 5;
    const int bp   = lane;
    const int hlh  = warp & 1;
    const int ke   = warp >> 1;              // k-eighth 0..7
    const int khq  = ke >> 1;                // k-quarter 0..3 (mbar index)
    const int bid  = blockIdx.x;
    const int h0   = bid * 4;
    const int gid  = bid >> 5;               // this CTA's producer group
    const bool is_stager = ((warp % 5) == 0);    // warps 0,5,10,15
    const int  sq = warp / 5;                    // staged quarter (valid for stagers)

    // ---- stage Wsp once: Wsp[k*16 + hl*4 + g] = Wh[g*512 + h0 + hl][k]
    #pragma unroll
    for (int it = 0; it < 16; it++) {
        int idx = it * 512 + tid;            // 0..8191 = r*512 + k
        int r = idx >> 9, k = idx & 511;
        int hl = r >> 2, g = r & 3;
        Wsp[k * 16 + hl * 4 + g] = Wh[((size_t)(g * HID + h0 + hl)) * HID + k];
    }
    if (tid == 0) {
        #pragma unroll
        for (int q = 0; q < 4; q++) mbar_init(smem_u32(&mbar[q]), 1);
    }

    // epilogue threads: tid < 128 -> cell (ehl = tid>>5, ebp = tid&31)
    const bool epi = (tid < 128);
    const int ehl = tid >> 5;
    const int ebp = tid & 31;
    const int eh  = h0 + ehl;
    float c0 = 0.0f, c1 = 0.0f;

    const unsigned my_bar  = smem_u32(&mbar[khq]);
    const unsigned hs_dst0 = smem_u32(hs);

    __syncthreads();

    int cur = 0;
    for (int t = 0; t < T_LEN; t++) {
        // ---- gx prefetch (h-independent; overlaps the epoch wait)
        float2 gxf, gxi, gxo, gxc;
        if (epi) {
            const float* gp = g_gx + ((size_t)t * GH + eh) * BATCH + 2 * ebp;
            gxf = __ldg((const float2*)(gp + (size_t)0 * HID * BATCH));
            gxi = __ldg((const float2*)(gp + (size_t)1 * HID * BATCH));
            gxo = __ldg((const float2*)(gp + (size_t)2 * HID * BATCH));
            gxc = __ldg((const float2*)(gp + (size_t)3 * HID * BATCH));
        }

        // ---- per-quarter stager: wait for its producer group, then copy 32 KB
        if (is_stager && lane == 0) {
            if (t > 0) {
                while (g_epochs[sq] < (unsigned)t) { __nanosleep(32); }
            }
            mbar_expect_tx(smem_u32(&mbar[sq]), 32768u);
            bulk_g2s(hs_dst0 + (unsigned)sq * 32768u,
                     (const char*)g_h[cur] + (unsigned)sq * 32768u,
                     32768u, smem_u32(&mbar[sq]));
        }

        // ---- wait only for this warp's k-quarter
        mbar_wait(my_bar, (unsigned)(t & 1));

        // ---- compute: 64 k x (2 hl rows x 2 gate-pairs x 2 batches)
        float2 A000 = make_float2(0.f, 0.f), A001 = A000, A010 = A000, A011 = A000;
        float2 A100 = A000, A101 = A000, A110 = A000, A111 = A000;

        const float* wP = Wsp + (ke * 64) * 16 + 8 * hlh;
        const float* hP = hs + (ke * 64) * 64 + 2 * bp;

        #pragma unroll 8
        for (int kl = 0; kl < 64; kl++) {
            const float4 w4a = *(const float4*)(wP);       // rows: hl=2hlh, gates 0..3
            const float4 w4b = *(const float4*)(wP + 4);   // rows: hl=2hlh+1
            const float2 hv  = *(const float2*)(hP);
            const float2 d0 = make_float2(hv.x, hv.x);
            const float2 d1 = make_float2(hv.y, hv.y);
            const float2 w01a = make_float2(w4a.x, w4a.y);
            const float2 w23a = make_float2(w4a.z, w4a.w);
            const float2 w01b = make_float2(w4b.x, w4b.y);
            const float2 w23b = make_float2(w4b.z, w4b.w);
            A000 = ffma2(w01a, d0, A000);
            A001 = ffma2(w01a, d1, A001);
            A010 = ffma2(w23a, d0, A010);
            A011 = ffma2(w23a, d1, A011);
            A100 = ffma2(w01b, d0, A100);
            A101 = ffma2(w01b, d1, A101);
            A110 = ffma2(w23b, d0, A110);
            A111 = ffma2(w23b, d1, A111);
            wP += 16;
            hP += 64;
        }

        // ---- guard: previous step's red consumers must be done (skip at t=0)
        if (t > 0 && !epi) {
            asm volatile("bar.sync 2, 512;" ::: "memory");
        }

        // ---- scatter partials: red[((ke*4+hl)*2+gp)*64 + b] (f2 = gate pair)
        {
            const int hlA = 2 * hlh, hlB = 2 * hlh + 1;
            float4* r0 = (float4*)(red + ((ke * 4 + hlA) * 2 + 0) * 64 + 2 * bp);
            float4* r1 = (float4*)(red + ((ke * 4 + hlA) * 2 + 1) * 64 + 2 * bp);
            float4* r2 = (float4*)(red + ((ke * 4 + hlB) * 2 + 0) * 64 + 2 * bp);
            float4* r3 = (float4*)(red + ((ke * 4 + hlB) * 2 + 1) * 64 + 2 * bp);
            *r0 = make_float4(A000.x, A000.y, A001.x, A001.y);
            *r1 = make_float4(A010.x, A010.y, A011.x, A011.y);
            *r2 = make_float4(A100.x, A100.y, A101.x, A101.y);
            *r3 = make_float4(A110.x, A110.y, A111.x, A111.y);
        }
        __syncthreads();

        // ---- reduce 8 k-eighths + gates + publish (epi threads only)
        if (epi) {
            float2 s01_0 = make_float2(0.f, 0.f), s01_1 = s01_0;
            float2 s23_0 = s01_0, s23_1 = s01_0;
            #pragma unroll
            for (int q = 0; q < 8; q++) {
                const float4 v01 = *(const float4*)(red + ((q * 4 + ehl) * 2 + 0) * 64 + 2 * ebp);
                const float4 v23 = *(const float4*)(red + ((q * 4 + ehl) * 2 + 1) * 64 + 2 * ebp);
                s01_0 = fadd2(s01_0, make_float2(v01.x, v01.y));
                s01_1 = fadd2(s01_1, make_float2(v01.z, v01.w));
                s23_0 = fadd2(s23_0, make_float2(v23.x, v23.y));
                s23_1 = fadd2(s23_1, make_float2(v23.z, v23.w));
            }
            // s01 = (f, i), s23 = (o, c); gx already contains bx + bh
            const float pf0 = s01_0.x + gxf.x, pf1 = s01_1.x + gxf.y;
            const float pi0 = s01_0.y + gxi.x, pi1 = s01_1.y + gxi.y;
            const float po0 = s23_0.x + gxo.x, po1 = s23_1.x + gxo.y;
            const float pc0 = s23_0.y + gxc.x, pc1 = s23_1.y + gxc.y;

            const float f0 = fast_sigmoid(pf0), f1 = fast_sigmoid(pf1);
            const float i0 = fast_sigmoid(pi0), i1 = fast_sigmoid(pi1);
            const float o0 = fast_sigmoid(po0), o1 = fast_sigmoid(po1);
            const float q0 = fast_tanh(pc0),    q1 = fast_tanh(pc1);

            c0 = f0 * c0 + i0 * q0;
            c1 = f1 * c1 + i1 * q1;
            const float hn0 = o0 * fast_tanh(c0);
            const float hn1 = o1 * fast_tanh(c1);

            // publish next-step h first (only thing other CTAs wait on)
            __stcg((float2*)(g_h[cur ^ 1] + eh * BATCH + 2 * ebp),
                   make_float2(hn0, hn1));

            // red fully consumed (values folded into hn/c) -> release barrier 2
            asm volatile("bar.arrive 2, 512;" ::: "memory");

            // epi-only named barrier (warps 0-3, 128 threads), then release
            asm volatile("bar.sync 1, 128;" ::: "memory");
            if (tid == 0) {
                __threadfence();
                unsigned old = atomicAdd(&g_bars[gid], 1u);
                if (old == (unsigned)t * 32u + 31u) {
                    g_epochs[gid] = (unsigned)(t + 1);
                }
            }

            // off-critical-path outputs
            float* so = h_seq + ((size_t)t * BATCH + 2 * ebp) * HID + eh;
            so[0]   = hn0;
            so[HID] = hn1;
            if (t == T_LEN - 1) {
                out_hlast[(size_t)(2 * ebp) * HID + eh]     = hn0;
                out_hlast[(size_t)(2 * ebp + 1) * HID + eh] = hn1;
                out_clast[(size_t)(2 * ebp) * HID + eh]     = c0;
                out_clast[(size_t)(2 * ebp + 1) * HID + eh] = c1;
            }
        }

        cur ^= 1;
    }
}

// ---------------- launch ----------------
extern "C" void kernel_launch(void* const* d_in, const int* in_sizes, int n_in,
                              void* d_out, int out_size) {
    const float* x  = (const float*)d_in[0];
    const float* Wx = (const float*)d_in[1];
    const float* bx = (const float*)d_in[2];
    const float* Wh = (const float*)d_in[3];
    const float* bh = (const float*)d_in[4];

    float* out       = (float*)d_out;
    float* out_hlast = out + (size_t)T_LEN * BATCH * HID;
    float* out_clast = out_hlast + (size_t)BATCH * HID;

    const int gx_smem = (256 * 65 + 32 * 256) * sizeof(float);   // 99328 B
    const int ps_smem = (8192 + 32768 + 8192) * sizeof(float) + 64; // 196672 B
    cudaFuncSetAttribute(gx_kernel,       cudaFuncAttributeMaxDynamicSharedMemorySize, gx_smem);
    cudaFuncSetAttribute(lstm_persistent, cudaFuncAttributeMaxDynamicSharedMemorySize, ps_smem);

    init_state_kernel<<<128, 512>>>();
    gx_kernel<<<dim3(64, 512), 256, gx_smem>>>(x, Wx, bx, bh);
    lstm_persistent<<<NCTA, 512, ps_smem>>>(Wh, out, out_hlast, out_clast);
}